// round 1
// baseline (speedup 1.0000x reference)
#include <cuda_runtime.h>
#include <math.h>

#define D_IN  256
#define D_H   512
#define D_OUT 256
#define NB    8
#define BATCH 32768
#define ROWS  (9 * BATCH)   // 294912

// Scratch: __device__ globals (allocation-free rule)
__device__ float g_Xn[(size_t)ROWS * D_IN];   // 302 MB
__device__ float g_H [(size_t)ROWS * D_H];    // 604 MB
__device__ float g_F [(size_t)ROWS * D_OUT];  // 302 MB

// ---------------------------------------------------------------------------
// LayerNorm: one warp per row. Rows [0,B) = state, rows [B,9B) = neighbors flat.
// ---------------------------------------------------------------------------
__global__ __launch_bounds__(256) void ln_kernel(
    const float* __restrict__ state, const float* __restrict__ nbrs,
    const float* __restrict__ gamma, const float* __restrict__ beta,
    float* __restrict__ Xn, int B)
{
    int row  = blockIdx.x * 8 + (threadIdx.x >> 5);
    int lane = threadIdx.x & 31;
    const float* x = (row < B) ? state + (size_t)row * D_IN
                               : nbrs + (size_t)(row - B) * D_IN;
    float4 v0 = ((const float4*)x)[lane];
    float4 v1 = ((const float4*)x)[lane + 32];

    float s  = v0.x + v0.y + v0.z + v0.w + v1.x + v1.y + v1.z + v1.w;
    float ss = v0.x*v0.x + v0.y*v0.y + v0.z*v0.z + v0.w*v0.w
             + v1.x*v1.x + v1.y*v1.y + v1.z*v1.z + v1.w*v1.w;
#pragma unroll
    for (int o = 16; o; o >>= 1) {
        s  += __shfl_xor_sync(0xFFFFFFFFu, s,  o);
        ss += __shfl_xor_sync(0xFFFFFFFFu, ss, o);
    }
    float mu   = s * (1.0f / D_IN);
    float var  = ss * (1.0f / D_IN) - mu * mu;
    float rstd = rsqrtf(var + 1e-5f);

    float4 g0 = ((const float4*)gamma)[lane];
    float4 g1 = ((const float4*)gamma)[lane + 32];
    float4 be0 = ((const float4*)beta)[lane];
    float4 be1 = ((const float4*)beta)[lane + 32];

    float4 o0, o1;
    o0.x = (v0.x - mu) * rstd * g0.x + be0.x;
    o0.y = (v0.y - mu) * rstd * g0.y + be0.y;
    o0.z = (v0.z - mu) * rstd * g0.z + be0.z;
    o0.w = (v0.w - mu) * rstd * g0.w + be0.w;
    o1.x = (v1.x - mu) * rstd * g1.x + be1.x;
    o1.y = (v1.y - mu) * rstd * g1.y + be1.y;
    o1.z = (v1.z - mu) * rstd * g1.z + be1.z;
    o1.w = (v1.w - mu) * rstd * g1.w + be1.w;

    float* dst = Xn + (size_t)row * D_IN;
    ((float4*)dst)[lane]      = o0;
    ((float4*)dst)[lane + 32] = o1;
}

// ---------------------------------------------------------------------------
// SGEMM: C[M,N] = A[M,K] @ Bw[K,N] + bias[N], optional ReLU.
// 128x128 CTA tile, 8x8 per-thread microtile, K-step 8, double-buffered smem.
// ---------------------------------------------------------------------------
__global__ __launch_bounds__(256, 2) void sgemm_kernel(
    const float* __restrict__ A, const float* __restrict__ Bw,
    const float* __restrict__ bias, float* __restrict__ C,
    int M, int N, int K, int relu)
{
    __shared__ float As[2][8][132];   // [buf][k][m], padded stride vs bank conflicts
    __shared__ float Bs[2][8][128];   // [buf][k][n]

    int tid  = threadIdx.x;
    int row0 = blockIdx.y * 128;
    int col0 = blockIdx.x * 128;

    // Global load assignment
    int am = tid >> 1, ak = (tid & 1) * 4;     // A: 128 rows x 8 k
    int bk = tid >> 5, bn = (tid & 31) * 4;    // B: 8 k x 128 n
    const float* Aptr = A  + (size_t)(row0 + am) * K + ak;
    const float* Bptr = Bw + (size_t)bk * N + col0 + bn;

    // First tile
    {
        float4 a = *(const float4*)Aptr;
        float4 b = *(const float4*)Bptr;
        As[0][ak + 0][am] = a.x; As[0][ak + 1][am] = a.y;
        As[0][ak + 2][am] = a.z; As[0][ak + 3][am] = a.w;
        *(float4*)&Bs[0][bk][bn] = b;
    }
    __syncthreads();

    int trow = tid >> 4;   // 0..15
    int tcol = tid & 15;   // 0..15

    float acc[8][8];
#pragma unroll
    for (int i = 0; i < 8; i++)
#pragma unroll
        for (int j = 0; j < 8; j++) acc[i][j] = 0.0f;

    int nkt = K >> 3;
    for (int kt = 0; kt < nkt; ++kt) {
        int cur = kt & 1;
        float4 apre, bpre;
        if (kt + 1 < nkt) {
            apre = *(const float4*)(Aptr + (kt + 1) * 8);
            bpre = *(const float4*)(Bptr + (size_t)(kt + 1) * 8 * N);
        }
#pragma unroll
        for (int kk = 0; kk < 8; ++kk) {
            float4 a0 = *(const float4*)&As[cur][kk][trow * 8];
            float4 a1 = *(const float4*)&As[cur][kk][trow * 8 + 4];
            float4 b0 = *(const float4*)&Bs[cur][kk][tcol * 8];
            float4 b1 = *(const float4*)&Bs[cur][kk][tcol * 8 + 4];
            float ar[8] = {a0.x, a0.y, a0.z, a0.w, a1.x, a1.y, a1.z, a1.w};
            float br[8] = {b0.x, b0.y, b0.z, b0.w, b1.x, b1.y, b1.z, b1.w};
#pragma unroll
            for (int i = 0; i < 8; i++)
#pragma unroll
                for (int j = 0; j < 8; j++)
                    acc[i][j] = fmaf(ar[i], br[j], acc[i][j]);
        }
        if (kt + 1 < nkt) {
            int nxt = cur ^ 1;
            As[nxt][ak + 0][am] = apre.x; As[nxt][ak + 1][am] = apre.y;
            As[nxt][ak + 2][am] = apre.z; As[nxt][ak + 3][am] = apre.w;
            *(float4*)&Bs[nxt][bk][bn] = bpre;
        }
        __syncthreads();
    }

    // Epilogue: bias (+ ReLU), write C
    float bv[8];
#pragma unroll
    for (int j = 0; j < 8; j++) bv[j] = bias[col0 + tcol * 8 + j];

#pragma unroll
    for (int i = 0; i < 8; i++) {
        int r = row0 + trow * 8 + i;
        float* Crow = C + (size_t)r * N + col0 + tcol * 8;
#pragma unroll
        for (int j = 0; j < 8; j += 4) {
            float4 v;
            v.x = acc[i][j + 0] + bv[j + 0];
            v.y = acc[i][j + 1] + bv[j + 1];
            v.z = acc[i][j + 2] + bv[j + 2];
            v.w = acc[i][j + 3] + bv[j + 3];
            if (relu) {
                v.x = fmaxf(v.x, 0.0f); v.y = fmaxf(v.y, 0.0f);
                v.z = fmaxf(v.z, 0.0f); v.w = fmaxf(v.w, 0.0f);
            }
            *(float4*)(Crow + j) = v;
        }
    }
}

// ---------------------------------------------------------------------------
// Attention aggregation: one warp per batch element b.
// scores[n] = dot(F[B + n*B + b], attn_w) + attn_b; softmax over n;
// out[b] = F[b] + sum_n w_n * F_n
// ---------------------------------------------------------------------------
__global__ __launch_bounds__(256) void attn_kernel(
    const float* __restrict__ F, const float* __restrict__ aw,
    const float* __restrict__ ab_ptr, float* __restrict__ out, int B)
{
    int b    = blockIdx.x * 8 + (threadIdx.x >> 5);
    int lane = threadIdx.x & 31;
    float ab = ab_ptr[0];

    const float4* fl = (const float4*)(F + (size_t)b * D_OUT);
    float4 l0 = fl[lane], l1 = fl[lane + 32];
    float4 w0 = ((const float4*)aw)[lane];
    float4 w1 = ((const float4*)aw)[lane + 32];

    float4 nf[NB][2];
    float  sc[NB];
#pragma unroll
    for (int n = 0; n < NB; n++) {
        const float4* fp = (const float4*)(F + ((size_t)(1 + n) * B + b) * D_OUT);
        nf[n][0] = fp[lane];
        nf[n][1] = fp[lane + 32];
        float d = nf[n][0].x * w0.x + nf[n][0].y * w0.y
                + nf[n][0].z * w0.z + nf[n][0].w * w0.w
                + nf[n][1].x * w1.x + nf[n][1].y * w1.y
                + nf[n][1].z * w1.z + nf[n][1].w * w1.w;
#pragma unroll
        for (int o = 16; o; o >>= 1) d += __shfl_xor_sync(0xFFFFFFFFu, d, o);
        sc[n] = d + ab;
    }

    float mx = sc[0];
#pragma unroll
    for (int n = 1; n < NB; n++) mx = fmaxf(mx, sc[n]);
    float se = 0.0f;
#pragma unroll
    for (int n = 0; n < NB; n++) { sc[n] = expf(sc[n] - mx); se += sc[n]; }
    float inv = 1.0f / se;

    float4 o0 = l0, o1 = l1;
#pragma unroll
    for (int n = 0; n < NB; n++) {
        float wn = sc[n] * inv;
        o0.x = fmaf(wn, nf[n][0].x, o0.x);
        o0.y = fmaf(wn, nf[n][0].y, o0.y);
        o0.z = fmaf(wn, nf[n][0].z, o0.z);
        o0.w = fmaf(wn, nf[n][0].w, o0.w);
        o1.x = fmaf(wn, nf[n][1].x, o1.x);
        o1.y = fmaf(wn, nf[n][1].y, o1.y);
        o1.z = fmaf(wn, nf[n][1].z, o1.z);
        o1.w = fmaf(wn, nf[n][1].w, o1.w);
    }
    float* dst = out + (size_t)b * D_OUT;
    ((float4*)dst)[lane]      = o0;
    ((float4*)dst)[lane + 32] = o1;
}

// ---------------------------------------------------------------------------
extern "C" void kernel_launch(void* const* d_in, const int* in_sizes, int n_in,
                              void* d_out, int out_size)
{
    const float* state = (const float*)d_in[0];
    const float* nbrs  = (const float*)d_in[1];
    const float* gamma = (const float*)d_in[2];
    const float* beta  = (const float*)d_in[3];
    const float* W1    = (const float*)d_in[4];
    const float* b1    = (const float*)d_in[5];
    const float* W2    = (const float*)d_in[6];
    const float* b2    = (const float*)d_in[7];
    const float* aw    = (const float*)d_in[8];
    const float* ab    = (const float*)d_in[9];
    float* out = (float*)d_out;

    int B = in_sizes[0] / D_IN;   // 32768
    int R = 9 * B;                // 294912

    float *Xn, *H, *F;
    cudaGetSymbolAddress((void**)&Xn, g_Xn);
    cudaGetSymbolAddress((void**)&H,  g_H);
    cudaGetSymbolAddress((void**)&F,  g_F);

    ln_kernel<<<R / 8, 256>>>(state, nbrs, gamma, beta, Xn, B);
    sgemm_kernel<<<dim3(D_H / 128,  R / 128), 256>>>(Xn, W1, b1, H, R, D_H,  D_IN, 1);
    sgemm_kernel<<<dim3(D_OUT / 128, R / 128), 256>>>(H,  W2, b2, F, R, D_OUT, D_H, 0);
    attn_kernel<<<B / 8, 256>>>(F, aw, ab, out, B);
}

// round 3
// speedup vs baseline: 5.6397x; 5.6397x over previous
#include <cuda_runtime.h>
#include <cstdint>
#include <math.h>

#define D_IN  256
#define D_H   512
#define D_OUT 256
#define NB    8
#define ROWS  (9 * 32768)

#define MT  128    // CTA M tile
#define NTT 128    // CTA N tile
#define KC  32     // K chunk (floats) = 128 B/row

// Scratch (allocation-free rule)
__device__ float g_Xn [(size_t)ROWS * D_IN];
__device__ float g_H  [(size_t)ROWS * D_H];
__device__ float g_F  [(size_t)ROWS * D_OUT];
__device__ float g_W1T[(size_t)D_H * D_IN];    // [N=512][K=256]
__device__ float g_W2T[(size_t)D_OUT * D_H];   // [N=256][K=512]

// ---------------------------------------------------------------------------
__device__ __forceinline__ uint32_t smem_u32(const void* p) {
    uint32_t a;
    asm("{ .reg .u64 t; cvta.to.shared.u64 t, %1; cvt.u32.u64 %0, t; }" : "=r"(a) : "l"(p));
    return a;
}
__device__ __forceinline__ float round_tf32(float x) {
    uint32_t u;
    asm("cvt.rna.tf32.f32 %0, %1;" : "=r"(u) : "f"(x));
    return __uint_as_float(u);
}
__device__ __forceinline__ void cpa16(uint32_t s, const void* g) {
    asm volatile("cp.async.cg.shared.global [%0], [%1], 16;" :: "r"(s), "l"(g));
}
__device__ __forceinline__ void ldsm4(uint32_t* r, uint32_t addr) {
    asm volatile("ldmatrix.sync.aligned.m8n8.x4.shared.b16 {%0,%1,%2,%3}, [%4];"
                 : "=r"(r[0]), "=r"(r[1]), "=r"(r[2]), "=r"(r[3]) : "r"(addr));
}
__device__ __forceinline__ void mma_tf32(float* c, const uint32_t* a, const uint32_t* b) {
    asm volatile("mma.sync.aligned.m16n8k8.row.col.f32.tf32.tf32.f32 "
                 "{%0,%1,%2,%3}, {%4,%5,%6,%7}, {%8,%9}, {%0,%1,%2,%3};"
                 : "+f"(c[0]), "+f"(c[1]), "+f"(c[2]), "+f"(c[3])
                 : "r"(a[0]), "r"(a[1]), "r"(a[2]), "r"(a[3]), "r"(b[0]), "r"(b[1]));
}

// SMEM: [buf0 A 16K][buf0 B 16K][buf1 A 16K][buf1 B 16K] = 64 KB dynamic
#define TILE_BYTES (MT * KC * 4)   // 16384
#define SM_TOTAL   (4 * TILE_BYTES)

// ---------------------------------------------------------------------------
// tf32 mma.sync GEMM: C[M, n0:n0+128] = A[M,K] @ Bt[N,K]^T + bias (opt ReLU,
// opt tf32-round of the stored result).
// ---------------------------------------------------------------------------
__global__ void __launch_bounds__(256, 2) tc_gemm(
    const float* __restrict__ A, const float* __restrict__ Bt,
    const float* __restrict__ bias, float* __restrict__ C,
    int K, int ldc, int relu, int rnd)
{
    extern __shared__ char smem[];
    uint32_t sb = smem_u32(smem);
    const int tid = threadIdx.x, wid = tid >> 5, lane = tid & 31;
    const int row0 = blockIdx.y * MT;
    const int n0   = blockIdx.x * NTT;

    const uint32_t aoff[2] = { sb,                  sb + 2 * TILE_BYTES };
    const uint32_t boff[2] = { sb + TILE_BYTES,     sb + 3 * TILE_BYTES };

    // loader indices: 4 iters x 256 threads cover 128 rows x 8 col-blocks(16B)
    const int lr = tid >> 3;          // base row (stride 32 over iters)
    const int lc = tid & 7;           // col-block
    const float* Abase = A  + (size_t)row0 * K + lc * 4;
    const float* Bbase = Bt + (size_t)n0   * K + lc * 4;

    auto load_chunk = [&](int kt, int bi) {
        const float* Ap = Abase + kt * KC;
        const float* Bp = Bbase + kt * KC;
#pragma unroll
        for (int i = 0; i < 4; i++) {
            int r = lr + i * 32;
            uint32_t so = (uint32_t)(r * 128 + ((lc ^ (r & 7)) << 4));
            cpa16(aoff[bi] + so, Ap + (size_t)r * K);
            cpa16(boff[bi] + so, Bp + (size_t)r * K);
        }
        asm volatile("cp.async.commit_group;" ::: "memory");
    };

    const int wm = (wid >> 2) * 64;   // warp M offset
    const int wn = (wid & 3) * 32;    // warp N offset

    // per-thread ldmatrix row geometry (q = lane>>3 selects the 8x4 submatrix)
    const int q = lane >> 3;
    // A tile i: row = wm + i*16 + (q&1)*8 + (lane&7), cb = 2s + (q>>1)
    const int arow_base = wm + (q & 1) * 8 + (lane & 7);
    const int acb_add   = q >> 1;
    // B tile j2: row = wn + j2*16 + (q>>1)*8 + (lane&7), cb = 2s + (q&1)
    const int brow_base = wn + (q >> 1) * 8 + (lane & 7);
    const int bcb_add   = q & 1;

    float acc[4][4][4];
#pragma unroll
    for (int i = 0; i < 4; i++)
#pragma unroll
        for (int j = 0; j < 4; j++)
#pragma unroll
            for (int c = 0; c < 4; c++) acc[i][j][c] = 0.0f;

    const int nkt = K / KC;
    load_chunk(0, 0);

    for (int kt = 0; kt < nkt; kt++) {
        int b = kt & 1;
        if (kt + 1 < nkt) {
            load_chunk(kt + 1, b ^ 1);
            asm volatile("cp.async.wait_group 1;" ::: "memory");
        } else {
            asm volatile("cp.async.wait_group 0;" ::: "memory");
        }
        __syncthreads();

#pragma unroll
        for (int s = 0; s < 4; s++) {          // 4 x k8 substeps
            uint32_t af[4][4], bf[2][4];
#pragma unroll
            for (int i = 0; i < 4; i++) {
                int r = arow_base + i * 16;
                int cb = (2 * s + acb_add) ^ (r & 7);
                ldsm4(af[i], aoff[b] + (uint32_t)(r * 128 + cb * 16));
            }
#pragma unroll
            for (int j2 = 0; j2 < 2; j2++) {
                int r = brow_base + j2 * 16;
                int cb = (2 * s + bcb_add) ^ (r & 7);
                ldsm4(bf[j2], boff[b] + (uint32_t)(r * 128 + cb * 16));
            }
#pragma unroll
            for (int i = 0; i < 4; i++)
#pragma unroll
                for (int j = 0; j < 4; j++)
                    mma_tf32(acc[i][j], af[i], &bf[j >> 1][(j & 1) * 2]);
        }
        __syncthreads();
    }

    // epilogue
    const int g = lane >> 2, cpair = (lane & 3) * 2;
#pragma unroll
    for (int j = 0; j < 4; j++) {
        int col = n0 + wn + j * 8 + cpair;
        float b0 = bias[col], b1 = bias[col + 1];
#pragma unroll
        for (int i = 0; i < 4; i++) {
            int r = row0 + wm + i * 16 + g;
            float2 v0, v1;
            v0.x = acc[i][j][0] + b0;  v0.y = acc[i][j][1] + b1;
            v1.x = acc[i][j][2] + b0;  v1.y = acc[i][j][3] + b1;
            if (relu) {
                v0.x = fmaxf(v0.x, 0.0f); v0.y = fmaxf(v0.y, 0.0f);
                v1.x = fmaxf(v1.x, 0.0f); v1.y = fmaxf(v1.y, 0.0f);
            }
            if (rnd) {
                v0.x = round_tf32(v0.x); v0.y = round_tf32(v0.y);
                v1.x = round_tf32(v1.x); v1.y = round_tf32(v1.y);
            }
            *(float2*)(C + (size_t)r * ldc + col)       = v0;
            *(float2*)(C + (size_t)(r + 8) * ldc + col) = v1;
        }
    }
}

// ---------------------------------------------------------------------------
// Weight transpose with tf32 rounding: WT[c][r] = rna(W[r][c])
// ---------------------------------------------------------------------------
__global__ __launch_bounds__(256) void transpose_kernel(
    const float* __restrict__ W, float* __restrict__ WT, int R, int Cn)
{
    __shared__ float t[32][33];
    int bx = blockIdx.x * 32, by = blockIdx.y * 32;
    int x = threadIdx.x & 31, y = threadIdx.x >> 5;
#pragma unroll
    for (int i = 0; i < 32; i += 8)
        t[y + i][x] = W[(size_t)(by + y + i) * Cn + bx + x];
    __syncthreads();
#pragma unroll
    for (int i = 0; i < 32; i += 8)
        WT[(size_t)(bx + y + i) * R + by + x] = round_tf32(t[x][y + i]);
}

// ---------------------------------------------------------------------------
// LayerNorm (one warp/row), output tf32-rounded
// ---------------------------------------------------------------------------
__global__ __launch_bounds__(256) void ln_kernel(
    const float* __restrict__ state, const float* __restrict__ nbrs,
    const float* __restrict__ gamma, const float* __restrict__ beta,
    float* __restrict__ Xn, int B)
{
    int row  = blockIdx.x * 8 + (threadIdx.x >> 5);
    int lane = threadIdx.x & 31;
    const float* x = (row < B) ? state + (size_t)row * D_IN
                               : nbrs + (size_t)(row - B) * D_IN;
    float4 v0 = ((const float4*)x)[lane];
    float4 v1 = ((const float4*)x)[lane + 32];

    float s  = v0.x + v0.y + v0.z + v0.w + v1.x + v1.y + v1.z + v1.w;
    float ss = v0.x*v0.x + v0.y*v0.y + v0.z*v0.z + v0.w*v0.w
             + v1.x*v1.x + v1.y*v1.y + v1.z*v1.z + v1.w*v1.w;
#pragma unroll
    for (int o = 16; o; o >>= 1) {
        s  += __shfl_xor_sync(0xFFFFFFFFu, s,  o);
        ss += __shfl_xor_sync(0xFFFFFFFFu, ss, o);
    }
    float mu   = s * (1.0f / D_IN);
    float var  = ss * (1.0f / D_IN) - mu * mu;
    float rstd = rsqrtf(var + 1e-5f);

    float4 g0 = ((const float4*)gamma)[lane];
    float4 g1 = ((const float4*)gamma)[lane + 32];
    float4 be0 = ((const float4*)beta)[lane];
    float4 be1 = ((const float4*)beta)[lane + 32];

    float4 o0, o1;
    o0.x = round_tf32((v0.x - mu) * rstd * g0.x + be0.x);
    o0.y = round_tf32((v0.y - mu) * rstd * g0.y + be0.y);
    o0.z = round_tf32((v0.z - mu) * rstd * g0.z + be0.z);
    o0.w = round_tf32((v0.w - mu) * rstd * g0.w + be0.w);
    o1.x = round_tf32((v1.x - mu) * rstd * g1.x + be1.x);
    o1.y = round_tf32((v1.y - mu) * rstd * g1.y + be1.y);
    o1.z = round_tf32((v1.z - mu) * rstd * g1.z + be1.z);
    o1.w = round_tf32((v1.w - mu) * rstd * g1.w + be1.w);

    float* dst = Xn + (size_t)row * D_IN;
    ((float4*)dst)[lane]      = o0;
    ((float4*)dst)[lane + 32] = o1;
}

// ---------------------------------------------------------------------------
// Attention aggregation (one warp/batch element) — unchanged from R1
// ---------------------------------------------------------------------------
__global__ __launch_bounds__(256) void attn_kernel(
    const float* __restrict__ F, const float* __restrict__ aw,
    const float* __restrict__ ab_ptr, float* __restrict__ out, int B)
{
    int b    = blockIdx.x * 8 + (threadIdx.x >> 5);
    int lane = threadIdx.x & 31;
    float ab = ab_ptr[0];

    const float4* fl = (const float4*)(F + (size_t)b * D_OUT);
    float4 l0 = fl[lane], l1 = fl[lane + 32];
    float4 w0 = ((const float4*)aw)[lane];
    float4 w1 = ((const float4*)aw)[lane + 32];

    float4 nf[NB][2];
    float  sc[NB];
#pragma unroll
    for (int n = 0; n < NB; n++) {
        const float4* fp = (const float4*)(F + ((size_t)(1 + n) * B + b) * D_OUT);
        nf[n][0] = fp[lane];
        nf[n][1] = fp[lane + 32];
        float d = nf[n][0].x * w0.x + nf[n][0].y * w0.y
                + nf[n][0].z * w0.z + nf[n][0].w * w0.w
                + nf[n][1].x * w1.x + nf[n][1].y * w1.y
                + nf[n][1].z * w1.z + nf[n][1].w * w1.w;
#pragma unroll
        for (int o = 16; o; o >>= 1) d += __shfl_xor_sync(0xFFFFFFFFu, d, o);
        sc[n] = d + ab;
    }

    float mx = sc[0];
#pragma unroll
    for (int n = 1; n < NB; n++) mx = fmaxf(mx, sc[n]);
    float se = 0.0f;
#pragma unroll
    for (int n = 0; n < NB; n++) { sc[n] = expf(sc[n] - mx); se += sc[n]; }
    float inv = 1.0f / se;

    float4 o0 = l0, o1 = l1;
#pragma unroll
    for (int n = 0; n < NB; n++) {
        float wn = sc[n] * inv;
        o0.x = fmaf(wn, nf[n][0].x, o0.x);
        o0.y = fmaf(wn, nf[n][0].y, o0.y);
        o0.z = fmaf(wn, nf[n][0].z, o0.z);
        o0.w = fmaf(wn, nf[n][0].w, o0.w);
        o1.x = fmaf(wn, nf[n][1].x, o1.x);
        o1.y = fmaf(wn, nf[n][1].y, o1.y);
        o1.z = fmaf(wn, nf[n][1].z, o1.z);
        o1.w = fmaf(wn, nf[n][1].w, o1.w);
    }
    float* dst = out + (size_t)b * D_OUT;
    ((float4*)dst)[lane]      = o0;
    ((float4*)dst)[lane + 32] = o1;
}

// ---------------------------------------------------------------------------
extern "C" void kernel_launch(void* const* d_in, const int* in_sizes, int n_in,
                              void* d_out, int out_size)
{
    const float* state = (const float*)d_in[0];
    const float* nbrs  = (const float*)d_in[1];
    const float* gamma = (const float*)d_in[2];
    const float* beta  = (const float*)d_in[3];
    const float* W1    = (const float*)d_in[4];
    const float* b1    = (const float*)d_in[5];
    const float* W2    = (const float*)d_in[6];
    const float* b2    = (const float*)d_in[7];
    const float* aw    = (const float*)d_in[8];
    const float* ab    = (const float*)d_in[9];
    float* out = (float*)d_out;

    int B = in_sizes[0] / D_IN;   // 32768
    int R = 9 * B;                // 294912

    float *Xn, *H, *F, *W1T, *W2T;
    cudaGetSymbolAddress((void**)&Xn,  g_Xn);
    cudaGetSymbolAddress((void**)&H,   g_H);
    cudaGetSymbolAddress((void**)&F,   g_F);
    cudaGetSymbolAddress((void**)&W1T, g_W1T);
    cudaGetSymbolAddress((void**)&W2T, g_W2T);

    cudaFuncSetAttribute(tc_gemm, cudaFuncAttributeMaxDynamicSharedMemorySize, SM_TOTAL);

    transpose_kernel<<<dim3(D_H / 32,  D_IN / 32), 256>>>(W1, W1T, D_IN, D_H);
    transpose_kernel<<<dim3(D_OUT / 32, D_H / 32), 256>>>(W2, W2T, D_H, D_OUT);
    ln_kernel<<<R / 8, 256>>>(state, nbrs, gamma, beta, Xn, B);

    // H = rna(relu(Xn @ W1 + b1))
    tc_gemm<<<dim3(D_H / NTT,  R / MT), 256, SM_TOTAL>>>(Xn, W1T, b1, H, D_IN, D_H, 1, 1);
    // F = H @ W2 + b2
    tc_gemm<<<dim3(D_OUT / NTT, R / MT), 256, SM_TOTAL>>>(H, W2T, b2, F, D_H, D_OUT, 0, 0);

    attn_kernel<<<B / 8, 256>>>(F, aw, ab, out, B);
}